// round 14
// baseline (speedup 1.0000x reference)
#include <cuda_runtime.h>

typedef unsigned int u32;
typedef unsigned long long u64;

#define NUM_HEADS 16
#define BATCH     2
#define SEQ       4096
#define DMODEL    1024
#define HD        64

// ---- scratch (device globals: no allocation anywhere) ----
__device__ float g_q[BATCH * NUM_HEADS * SEQ * HD];      // [B,H,S,hd]
__device__ float g_k[BATCH * NUM_HEADS * SEQ * HD];
__device__ float g_v[BATCH * NUM_HEADS * SEQ * HD];
__device__ float g_attn[BATCH * SEQ * DMODEL];           // [B,S,D]

// ---- helpers ----
__device__ __forceinline__ u32 tf32r(float x) {
    u32 r; asm("cvt.rna.tf32.f32 %0, %1;" : "=r"(r) : "f"(x)); return r;
}
__device__ __forceinline__ float ex2f(float x) {
    float y; asm("ex2.approx.f32 %0, %1;" : "=f"(y) : "f"(x)); return y;
}
// D += A(16x8 tf32) * B(8x8 tf32), fp32 accum
__device__ __forceinline__ void mma8(float* d, const u32* a, const u32* b) {
    asm("mma.sync.aligned.m16n8k8.row.col.f32.tf32.tf32.f32 "
        "{%0,%1,%2,%3}, {%4,%5,%6,%7}, {%8,%9}, {%0,%1,%2,%3};"
        : "+f"(d[0]), "+f"(d[1]), "+f"(d[2]), "+f"(d[3])
        : "r"(a[0]), "r"(a[1]), "r"(a[2]), "r"(a[3]), "r"(b[0]), "r"(b[1]));
}
__device__ __forceinline__ uint4 hi4(const float4& v) {
    uint4 h; h.x = tf32r(v.x); h.y = tf32r(v.y); h.z = tf32r(v.z); h.w = tf32r(v.w);
    return h;
}
__device__ __forceinline__ uint4 lo4(const float4& v, const uint4& h) {
    uint4 l;
    l.x = tf32r(v.x - __uint_as_float(h.x));
    l.y = tf32r(v.y - __uint_as_float(h.y));
    l.z = tf32r(v.z - __uint_as_float(h.z));
    l.w = tf32r(v.w - __uint_as_float(h.w));
    return l;
}

// =====================================================================
// GEMM: C[M,N] = A[M,K] * W[N,K]^T, K=1024, via m16n8k8 tf32 MMA.
// (unchanged from R13: 128x128 tile, 2 CTAs/SM, THREE=1 -> 3xTF32)
// =====================================================================
#define AP 20
#define TILE_U32 (128 * AP)
#define GSM1 (4 * TILE_U32 * 4)
#define GSM3 (8 * TILE_U32 * 4)

template<int QKV, int THREE>
__global__ void __launch_bounds__(256, 2) gemm_tf32(
    const float* __restrict__ A, const float* __restrict__ W, float* __restrict__ Out)
{
    extern __shared__ u32 sh[];
    u32* Ah = sh;
    u32* Bh = Ah + 2 * TILE_U32;
    u32* Al = Bh + 2 * TILE_U32;
    u32* Bl = Al + 2 * TILE_U32;

    const int tid  = threadIdx.x;
    const int lane = tid & 31, wid = tid >> 5;
    const int g = lane >> 2, t = lane & 3;
    const int wm = wid >> 2, wn = wid & 3;
    const int bm = blockIdx.y, bn = blockIdx.x;

    const int sr = tid >> 2;
    const int sc = (tid & 3) << 2;

    const float* Ag = A + (u64)(bm * 128 + sr) * DMODEL + sc;
    const float* Wg = W + (u64)(bn * 128 + sr) * DMODEL + sc;

    float acc[4][4][4];
#pragma unroll
    for (int i = 0; i < 4; i++)
#pragma unroll
        for (int j = 0; j < 4; j++)
#pragma unroll
            for (int c = 0; c < 4; c++) acc[i][j][c] = 0.f;

    {
        float4 a0 = *(const float4*)(Ag);
        float4 a1 = *(const float4*)(Ag + 64 * DMODEL);
        float4 w0 = *(const float4*)(Wg);
        float4 w1 = *(const float4*)(Wg + 64 * DMODEL);
        uint4 h;
        h = hi4(a0); *(uint4*)&Ah[sr * AP + sc] = h;
        if (THREE) *(uint4*)&Al[sr * AP + sc] = lo4(a0, h);
        h = hi4(a1); *(uint4*)&Ah[(sr + 64) * AP + sc] = h;
        if (THREE) *(uint4*)&Al[(sr + 64) * AP + sc] = lo4(a1, h);
        h = hi4(w0); *(uint4*)&Bh[sr * AP + sc] = h;
        if (THREE) *(uint4*)&Bl[sr * AP + sc] = lo4(w0, h);
        h = hi4(w1); *(uint4*)&Bh[(sr + 64) * AP + sc] = h;
        if (THREE) *(uint4*)&Bl[(sr + 64) * AP + sc] = lo4(w1, h);
    }
    __syncthreads();

    const int NT = DMODEL / 16;
#pragma unroll 1
    for (int kt = 0; kt < NT; kt++) {
        float4 pa0, pa1, pw0, pw1;
        if (kt + 1 < NT) {
            const float* Ap = Ag + (kt + 1) * 16;
            const float* Wp = Wg + (kt + 1) * 16;
            pa0 = *(const float4*)(Ap);
            pa1 = *(const float4*)(Ap + 64 * DMODEL);
            pw0 = *(const float4*)(Wp);
            pw1 = *(const float4*)(Wp + 64 * DMODEL);
        }
        const int base = (kt & 1) * TILE_U32;
#pragma unroll
        for (int k8 = 0; k8 < 2; k8++) {
            const int co = k8 * 8 + t;
            u32 ah[4][4], al[4][4];
#pragma unroll
            for (int mf = 0; mf < 4; mf++) {
                int r0 = wm * 64 + mf * 16 + g;
                ah[mf][0] = Ah[base + r0 * AP + co];
                ah[mf][1] = Ah[base + (r0 + 8) * AP + co];
                ah[mf][2] = Ah[base + r0 * AP + co + 4];
                ah[mf][3] = Ah[base + (r0 + 8) * AP + co + 4];
                if (THREE) {
                    al[mf][0] = Al[base + r0 * AP + co];
                    al[mf][1] = Al[base + (r0 + 8) * AP + co];
                    al[mf][2] = Al[base + r0 * AP + co + 4];
                    al[mf][3] = Al[base + (r0 + 8) * AP + co + 4];
                }
            }
            u32 bh[4][2], bl[4][2];
#pragma unroll
            for (int nf = 0; nf < 4; nf++) {
                int rn = wn * 32 + nf * 8 + g;
                bh[nf][0] = Bh[base + rn * AP + co];
                bh[nf][1] = Bh[base + rn * AP + co + 4];
                if (THREE) {
                    bl[nf][0] = Bl[base + rn * AP + co];
                    bl[nf][1] = Bl[base + rn * AP + co + 4];
                }
            }
#pragma unroll
            for (int mf = 0; mf < 4; mf++)
#pragma unroll
                for (int nf = 0; nf < 4; nf++) {
                    mma8(acc[mf][nf], ah[mf], bh[nf]);
                    if (THREE) {
                        mma8(acc[mf][nf], ah[mf], bl[nf]);
                        mma8(acc[mf][nf], al[mf], bh[nf]);
                    }
                }
        }
        if (kt + 1 < NT) {
            const int nb = ((kt + 1) & 1) * TILE_U32;
            uint4 h;
            h = hi4(pa0); *(uint4*)&Ah[nb + sr * AP + sc] = h;
            if (THREE) *(uint4*)&Al[nb + sr * AP + sc] = lo4(pa0, h);
            h = hi4(pa1); *(uint4*)&Ah[nb + (sr + 64) * AP + sc] = h;
            if (THREE) *(uint4*)&Al[nb + (sr + 64) * AP + sc] = lo4(pa1, h);
            h = hi4(pw0); *(uint4*)&Bh[nb + sr * AP + sc] = h;
            if (THREE) *(uint4*)&Bl[nb + sr * AP + sc] = lo4(pw0, h);
            h = hi4(pw1); *(uint4*)&Bh[nb + (sr + 64) * AP + sc] = h;
            if (THREE) *(uint4*)&Bl[nb + (sr + 64) * AP + sc] = lo4(pw1, h);
        }
        __syncthreads();
    }

#pragma unroll
    for (int mf = 0; mf < 4; mf++) {
#pragma unroll
        for (int nf = 0; nf < 4; nf++) {
            int m = bm * 128 + wm * 64 + mf * 16 + g;
            int n = bn * 128 + wn * 32 + nf * 8 + 2 * t;
            float2 v0 = make_float2(acc[mf][nf][0], acc[mf][nf][1]);
            float2 v1 = make_float2(acc[mf][nf][2], acc[mf][nf][3]);
            if (QKV) {
                int b = m >> 12, h = n >> 6, d = n & 63;
                int s0 = m & (SEQ - 1);
                float* p = Out + (u64)((b * NUM_HEADS + h) * SEQ) * HD + d;
                *(float2*)(p + (u64)s0 * HD)       = v0;
                *(float2*)(p + (u64)(s0 + 8) * HD) = v1;
            } else {
                *(float2*)(Out + (u64)m * DMODEL + n)       = v0;
                *(float2*)(Out + (u64)(m + 8) * DMODEL + n) = v1;
            }
        }
    }
}

// =====================================================================
// Causal flash attention with FRAGMENT-NATIVE smem layouts.
//   QF [wid][k8][lane] uint4 (Q-hi A-frag), per-(wid,k8) pitch 132 u32
//   KF [k8]{pitch 1028}[nf][lane] uint4 = {Kh@co, Kh@co+4, Kl@co, Kl@co+4}
//   Vs [64][72] plain (R13 layout, conflict-free)
//   Q-lo A-frags in 32 persistent registers (staged via KF/Vs region).
// Inner loop: 1 LDS.128 (A) + 8 LDS.128 (B hi+lo) per k8 in GEMM1.
// =====================================================================
#define QFP 132                     // u32 pitch per (wid,k8) block (16B mult)
#define KFP 1028                    // u32 pitch per k8 block (16B mult)
#define QF_U32 (64 * QFP)           // 8 wid * 8 k8 * 132
#define KF_U32 (8 * KFP)
#define VP 72
#define VS_U32 (64 * VP)
#define ATSM ((QF_U32 + KF_U32 + VS_U32) * 4)   // 85120 B

__global__ void __launch_bounds__(256, 2) attn_tf32(
    const float* __restrict__ Q,
    const float* __restrict__ K,
    const float* __restrict__ V,
    float* __restrict__ O)
{
    extern __shared__ u32 sh[];
    u32* QF = sh;                    // Q-hi frags
    u32* KF = QF + QF_U32;           // K hi/lo frags
    u32* Vs = KF + KF_U32;           // V plain
    u32* QLT = KF;                   // Q-lo staging temp (fits in KF+Vs)

    const int tid  = threadIdx.x;
    const int lane = tid & 31, wid = tid >> 5;
    const int g = lane >> 2, t = lane & 3;
    const int qi = (gridDim.x - 1) - blockIdx.x;   // longest-work CTAs first
    const int bh = blockIdx.y;
    const int q0 = qi * 128;
    const int r0 = wid * 16 + g;

    const float* Qbh = Q + (u64)bh * SEQ * HD;
    const float* Kbh = K + (u64)bh * SEQ * HD;
    const float* Vbh = V + (u64)bh * SEQ * HD;

    const float QSCALE = 0.125f * 1.4426950408889634f;  // 1/sqrt(64)*log2(e)

    // ---- stage Q: scale, hi/lo split, write frag-native (hi->QF, lo->QLT) ----
#pragma unroll
    for (int kk = 0; kk < 8; kk++) {
        int it = tid + kk * 256;
        int r = it >> 4;                 // 0..127
        int c4 = (it & 15) << 2;         // 0,4,...,60
        float4 v = *(const float4*)(Qbh + (u64)(q0 + r) * HD + c4);
        v.x *= QSCALE; v.y *= QSCALE; v.z *= QSCALE; v.w *= QSCALE;
        uint4 h4 = hi4(v);
        uint4 l4 = lo4(v, h4);
        int w  = r >> 4, rr = r & 15;
        int gg = rr & 7, half = rr >> 3;
        int k8 = c4 >> 3, hh = (c4 >> 2) & 1;
        u32* qb = QF  + (w * 8 + k8) * QFP + gg * 16 + half + 2 * hh;
        u32* lb = QLT + (w * 8 + k8) * QFP + gg * 16 + half + 2 * hh;
        qb[0]  = h4.x; qb[4]  = h4.y; qb[8]  = h4.z; qb[12] = h4.w;
        lb[0]  = l4.x; lb[4]  = l4.y; lb[8]  = l4.z; lb[12] = l4.w;
    }
    __syncthreads();

    // Q-lo A-frags -> persistent registers
    u32 ql[8][4];
    {
        const u32* qlb = QLT + wid * (8 * QFP) + (lane << 2);
#pragma unroll
        for (int k8 = 0; k8 < 8; k8++) {
            uint4 a4 = *(const uint4*)(qlb + k8 * QFP);
            ql[k8][0] = a4.x; ql[k8][1] = a4.y; ql[k8][2] = a4.z; ql[k8][3] = a4.w;
        }
    }
    __syncthreads();   // before K staging overwrites QLT region

    float of[8][4];
    float m_i[2], l_i[2];
#pragma unroll
    for (int nf = 0; nf < 8; nf++)
#pragma unroll
        for (int c = 0; c < 4; c++) of[nf][c] = 0.f;
    m_i[0] = m_i[1] = -1e30f;
    l_i[0] = l_i[1] = 0.f;

    const int NJ = 2 * qi + 2;
    for (int jt = 0; jt < NJ; jt++) {
        const int j0 = jt * 64;

        // ---- stage K (frag-native hi/lo) and V (plain tf32) ----
#pragma unroll
        for (int kk = 0; kk < 4; kk++) {
            int it = tid + kk * 256;
            int r = it >> 4;                 // 0..63
            int c4 = (it & 15) << 2;
            float4 kv = *(const float4*)(Kbh + (u64)(j0 + r) * HD + c4);
            uint4 h4 = hi4(kv);
            uint4 l4 = lo4(kv, h4);
            int nf = r >> 3, gg = r & 7;
            int k8 = c4 >> 3, hh = (c4 >> 2) & 1;
            u32* kb = KF + k8 * KFP + nf * 128 + gg * 16 + hh;
            kb[0]  = h4.x; kb[4]  = h4.y; kb[8]  = h4.z; kb[12] = h4.w;
            kb[2]  = l4.x; kb[6]  = l4.y; kb[10] = l4.z; kb[14] = l4.w;
            float4 vv = *(const float4*)(Vbh + (u64)(j0 + r) * HD + c4);
            *(uint4*)&Vs[r * VP + c4] = hi4(vv);
        }
        __syncthreads();

        // ---- GEMM1: S = Q K^T  (3xTF32), frag-native reads ----
        float sf[8][4];
#pragma unroll
        for (int nf = 0; nf < 8; nf++)
#pragma unroll
            for (int c = 0; c < 4; c++) sf[nf][c] = 0.f;

        const u32* qf = QF + wid * (8 * QFP) + (lane << 2);
        const u32* kf = KF + (lane << 2);
#pragma unroll
        for (int k8 = 0; k8 < 8; k8++) {
            uint4 a4 = *(const uint4*)(qf + k8 * QFP);
            u32 ah[4] = {a4.x, a4.y, a4.z, a4.w};
            const u32* kfk = kf + k8 * KFP;
#pragma unroll
            for (int nf = 0; nf < 8; nf++) {
                uint4 b4 = *(const uint4*)(kfk + nf * 128);
                u32 bhh[2] = {b4.x, b4.y};
                u32 bll[2] = {b4.z, b4.w};
                mma8(sf[nf], ah, bhh);
                mma8(sf[nf], ah, bll);
                mma8(sf[nf], ql[k8], bhh);
            }
        }

        // ---- causal mask (diagonal tiles only) ----
        if (jt >= 2 * qi) {
            int rg0 = q0 + r0, rg1 = rg0 + 8;
#pragma unroll
            for (int nf = 0; nf < 8; nf++) {
                int c0 = j0 + nf * 8 + 2 * t;
                if (c0     > rg0) sf[nf][0] = -1e30f;
                if (c0 + 1 > rg0) sf[nf][1] = -1e30f;
                if (c0     > rg1) sf[nf][2] = -1e30f;
                if (c0 + 1 > rg1) sf[nf][3] = -1e30f;
            }
        }

        // ---- online softmax (base-2); rows live in a quad -> 2 shuffles ----
#pragma unroll
        for (int r = 0; r < 2; r++) {
            float mx = -1e30f;
#pragma unroll
            for (int nf = 0; nf < 8; nf++)
                mx = fmaxf(mx, fmaxf(sf[nf][2 * r], sf[nf][2 * r + 1]));
            mx = fmaxf(mx, __shfl_xor_sync(0xffffffffu, mx, 1));
            mx = fmaxf(mx, __shfl_xor_sync(0xffffffffu, mx, 2));
            float mn = fmaxf(m_i[r], mx);
            float alpha = ex2f(m_i[r] - mn);
            float rs = 0.f;
#pragma unroll
            for (int nf = 0; nf < 8; nf++) {
                float p0 = ex2f(sf[nf][2 * r] - mn);
                float p1 = ex2f(sf[nf][2 * r + 1] - mn);
                sf[nf][2 * r] = p0; sf[nf][2 * r + 1] = p1;
                rs += p0 + p1;
            }
            rs += __shfl_xor_sync(0xffffffffu, rs, 1);
            rs += __shfl_xor_sync(0xffffffffu, rs, 2);
            l_i[r] = l_i[r] * alpha + rs;
            m_i[r] = mn;
#pragma unroll
            for (int nf = 0; nf < 8; nf++) {
                of[nf][2 * r]     *= alpha;
                of[nf][2 * r + 1] *= alpha;
            }
        }

        // ---- P: tf32 convert, C-frag -> A-frag via warp shuffles ----
        u32 pt[8][4];
#pragma unroll
        for (int nf = 0; nf < 8; nf++)
#pragma unroll
            for (int c = 0; c < 4; c++) pt[nf][c] = tf32r(sf[nf][c]);

        const int srcA = (lane & 28) | (t >> 1);

        // ---- GEMM2: O += P V  (single tf32) ----
#pragma unroll
        for (int k8 = 0; k8 < 8; k8++) {
            u32 pa[4], v0, v1;
            v0 = __shfl_sync(0xffffffffu, pt[k8][0], srcA);
            v1 = __shfl_sync(0xffffffffu, pt[k8][1], srcA);
            pa[0] = (t & 1) ? v1 : v0;
            v0 = __shfl_sync(0xffffffffu, pt[k8][2], srcA);
            v1 = __shfl_sync(0xffffffffu, pt[k8][3], srcA);
            pa[1] = (t & 1) ? v1 : v0;
            v0 = __shfl_sync(0xffffffffu, pt[k8][0], srcA + 2);
            v1 = __shfl_sync(0xffffffffu, pt[k8][1], srcA + 2);
            pa[2] = (t & 1) ? v1 : v0;
            v0 = __shfl_sync(0xffffffffu, pt[k8][2], srcA + 2);
            v1 = __shfl_sync(0xffffffffu, pt[k8][3], srcA + 2);
            pa[3] = (t & 1) ? v1 : v0;
#pragma unroll
            for (int nf = 0; nf < 8; nf++) {
                u32 vb[2] = { Vs[(k8 * 8 + t) * VP + nf * 8 + g],
                              Vs[(k8 * 8 + t + 4) * VP + nf * 8 + g] };
                mma8(of[nf], pa, vb);
            }
        }
        __syncthreads();   // protect KF/Vs before next tile's staging
    }

    // ---- epilogue: O /= l, write [B,S,D] slice ----
    const int b = bh >> 4, h = bh & 15;
#pragma unroll
    for (int r = 0; r < 2; r++) {
        float inv = 1.0f / l_i[r];
        int row = q0 + r0 + 8 * r;
        float* p = O + (u64)(b * SEQ + row) * DMODEL + h * HD;
#pragma unroll
        for (int nf = 0; nf < 8; nf++) {
            *(float2*)(p + nf * 8 + 2 * t) =
                make_float2(of[nf][2 * r] * inv, of[nf][2 * r + 1] * inv);
        }
    }
}

// =====================================================================
extern "C" void kernel_launch(void* const* d_in, const int* in_sizes, int n_in,
                              void* d_out, int out_size)
{
    (void)in_sizes; (void)n_in; (void)out_size;
    const float* X  = (const float*)d_in[0];
    const float* Wq = (const float*)d_in[1];
    const float* Wk = (const float*)d_in[2];
    const float* Wv = (const float*)d_in[3];
    const float* Wo = (const float*)d_in[4];
    float* out = (float*)d_out;

    float *gq, *gk, *gv, *ga;
    cudaGetSymbolAddress((void**)&gq, g_q);
    cudaGetSymbolAddress((void**)&gk, g_k);
    cudaGetSymbolAddress((void**)&gv, g_v);
    cudaGetSymbolAddress((void**)&ga, g_attn);

    cudaFuncSetAttribute(gemm_tf32<1,1>, cudaFuncAttributeMaxDynamicSharedMemorySize, GSM3);
    cudaFuncSetAttribute(gemm_tf32<1,0>, cudaFuncAttributeMaxDynamicSharedMemorySize, GSM1);
    cudaFuncSetAttribute(gemm_tf32<0,0>, cudaFuncAttributeMaxDynamicSharedMemorySize, GSM1);
    cudaFuncSetAttribute(attn_tf32,      cudaFuncAttributeMaxDynamicSharedMemorySize, ATSM);

    dim3 ggrid(DMODEL / 128, (BATCH * SEQ) / 128);   // (8, 64)

    // 1) projections: Q,K in 3xTF32 (score path), V single tf32
    gemm_tf32<1,1><<<ggrid, 256, GSM3>>>(X, Wq, gq);
    gemm_tf32<1,1><<<ggrid, 256, GSM3>>>(X, Wk, gk);
    gemm_tf32<1,0><<<ggrid, 256, GSM1>>>(X, Wv, gv);

    // 2) causal flash attention -> g_attn [B,S,D]
    attn_tf32<<<dim3(SEQ / 128, BATCH * NUM_HEADS), 256, ATSM>>>(gq, gk, gv, ga);

    // 3) output projection -> d_out (single tf32)
    gemm_tf32<0,0><<<ggrid, 256, GSM1>>>(ga, Wo, out);
}

// round 15
// speedup vs baseline: 1.2191x; 1.2191x over previous
#include <cuda_runtime.h>

typedef unsigned int u32;
typedef unsigned long long u64;

#define NUM_HEADS 16
#define BATCH     2
#define SEQ       4096
#define DMODEL    1024
#define HD        64

// ---- scratch (device globals: no allocation anywhere) ----
__device__ float g_q[BATCH * NUM_HEADS * SEQ * HD];      // [B,H,S,hd]
__device__ float g_k[BATCH * NUM_HEADS * SEQ * HD];
__device__ float g_v[BATCH * NUM_HEADS * SEQ * HD];
__device__ float g_attn[BATCH * SEQ * DMODEL];           // [B,S,D]

// ---- helpers ----
__device__ __forceinline__ u32 tf32r(float x) {
    u32 r; asm("cvt.rna.tf32.f32 %0, %1;" : "=r"(r) : "f"(x)); return r;
}
__device__ __forceinline__ float ex2f(float x) {
    float y; asm("ex2.approx.f32 %0, %1;" : "=f"(y) : "f"(x)); return y;
}
// D += A(16x8 tf32) * B(8x8 tf32), fp32 accum
__device__ __forceinline__ void mma8(float* d, const u32* a, const u32* b) {
    asm("mma.sync.aligned.m16n8k8.row.col.f32.tf32.tf32.f32 "
        "{%0,%1,%2,%3}, {%4,%5,%6,%7}, {%8,%9}, {%0,%1,%2,%3};"
        : "+f"(d[0]), "+f"(d[1]), "+f"(d[2]), "+f"(d[3])
        : "r"(a[0]), "r"(a[1]), "r"(a[2]), "r"(a[3]), "r"(b[0]), "r"(b[1]));
}
__device__ __forceinline__ uint4 hi4(const float4& v) {
    uint4 h; h.x = tf32r(v.x); h.y = tf32r(v.y); h.z = tf32r(v.z); h.w = tf32r(v.w);
    return h;
}
__device__ __forceinline__ uint4 lo4(const float4& v, const uint4& h) {
    uint4 l;
    l.x = tf32r(v.x - __uint_as_float(h.x));
    l.y = tf32r(v.y - __uint_as_float(h.y));
    l.z = tf32r(v.z - __uint_as_float(h.z));
    l.w = tf32r(v.w - __uint_as_float(h.w));
    return l;
}

#define AP 20
#define TILE_U32 (128 * AP)
#define GSM1 (4 * TILE_U32 * 4)
#define GSM3 (8 * TILE_U32 * 4)

// =====================================================================
// Merged QKV GEMM: one launch, grid.z selects Wq/Wk/Wv.
// z<2 (Q,K score path): 3xTF32 with distance-16 accumulator passes.
// z==2 (V): single tf32. Epilogue scatters to [B,H,S,hd]. 2 CTAs/SM.
// =====================================================================
__global__ void __launch_bounds__(256, 2) gemm_qkv(
    const float* __restrict__ A,
    const float* __restrict__ Wq, const float* __restrict__ Wk, const float* __restrict__ Wv,
    float* __restrict__ Oq, float* __restrict__ Ok, float* __restrict__ Ov)
{
    extern __shared__ u32 sh[];
    u32* Ah = sh;
    u32* Bh = Ah + 2 * TILE_U32;
    u32* Al = Bh + 2 * TILE_U32;
    u32* Bl = Al + 2 * TILE_U32;

    const int z = blockIdx.z;
    const float* W = (z == 0) ? Wq : (z == 1) ? Wk : Wv;
    float* Out     = (z == 0) ? Oq : (z == 1) ? Ok : Ov;
    const bool three = (z < 2);

    const int tid  = threadIdx.x;
    const int lane = tid & 31, wid = tid >> 5;
    const int g = lane >> 2, t = lane & 3;
    const int wm = wid >> 2, wn = wid & 3;
    const int bm = blockIdx.y, bn = blockIdx.x;

    const int sr = tid >> 2;
    const int sc = (tid & 3) << 2;

    const float* Ag = A + (u64)(bm * 128 + sr) * DMODEL + sc;
    const float* Wg = W + (u64)(bn * 128 + sr) * DMODEL + sc;

    float acc[4][4][4];
#pragma unroll
    for (int i = 0; i < 4; i++)
#pragma unroll
        for (int j = 0; j < 4; j++)
#pragma unroll
            for (int c = 0; c < 4; c++) acc[i][j][c] = 0.f;

    {
        float4 a0 = *(const float4*)(Ag);
        float4 a1 = *(const float4*)(Ag + 64 * DMODEL);
        float4 w0 = *(const float4*)(Wg);
        float4 w1 = *(const float4*)(Wg + 64 * DMODEL);
        uint4 h;
        h = hi4(a0); *(uint4*)&Ah[sr * AP + sc] = h;
        if (three) *(uint4*)&Al[sr * AP + sc] = lo4(a0, h);
        h = hi4(a1); *(uint4*)&Ah[(sr + 64) * AP + sc] = h;
        if (three) *(uint4*)&Al[(sr + 64) * AP + sc] = lo4(a1, h);
        h = hi4(w0); *(uint4*)&Bh[sr * AP + sc] = h;
        if (three) *(uint4*)&Bl[sr * AP + sc] = lo4(w0, h);
        h = hi4(w1); *(uint4*)&Bh[(sr + 64) * AP + sc] = h;
        if (three) *(uint4*)&Bl[(sr + 64) * AP + sc] = lo4(w1, h);
    }
    __syncthreads();

    const int NT = DMODEL / 16;
#pragma unroll 1
    for (int kt = 0; kt < NT; kt++) {
        float4 pa0, pa1, pw0, pw1;
        if (kt + 1 < NT) {
            const float* Ap = Ag + (kt + 1) * 16;
            const float* Wp = Wg + (kt + 1) * 16;
            pa0 = *(const float4*)(Ap);
            pa1 = *(const float4*)(Ap + 64 * DMODEL);
            pw0 = *(const float4*)(Wp);
            pw1 = *(const float4*)(Wp + 64 * DMODEL);
        }
        const int base = (kt & 1) * TILE_U32;
#pragma unroll
        for (int k8 = 0; k8 < 2; k8++) {
            const int co = k8 * 8 + t;
            u32 ah[4][4], al[4][4];
#pragma unroll
            for (int mf = 0; mf < 4; mf++) {
                int r0 = wm * 64 + mf * 16 + g;
                ah[mf][0] = Ah[base + r0 * AP + co];
                ah[mf][1] = Ah[base + (r0 + 8) * AP + co];
                ah[mf][2] = Ah[base + r0 * AP + co + 4];
                ah[mf][3] = Ah[base + (r0 + 8) * AP + co + 4];
                if (three) {
                    al[mf][0] = Al[base + r0 * AP + co];
                    al[mf][1] = Al[base + (r0 + 8) * AP + co];
                    al[mf][2] = Al[base + r0 * AP + co + 4];
                    al[mf][3] = Al[base + (r0 + 8) * AP + co + 4];
                }
            }
            u32 bh[4][2], bl[4][2];
#pragma unroll
            for (int nf = 0; nf < 4; nf++) {
                int rn = wn * 32 + nf * 8 + g;
                bh[nf][0] = Bh[base + rn * AP + co];
                bh[nf][1] = Bh[base + rn * AP + co + 4];
                if (three) {
                    bl[nf][0] = Bl[base + rn * AP + co];
                    bl[nf][1] = Bl[base + rn * AP + co + 4];
                }
            }
            // pass 1: hi*hi (distance-16 accumulator reuse)
#pragma unroll
            for (int mf = 0; mf < 4; mf++)
#pragma unroll
                for (int nf = 0; nf < 4; nf++)
                    mma8(acc[mf][nf], ah[mf], bh[nf]);
            if (three) {
                // pass 2: hi*lo
#pragma unroll
                for (int mf = 0; mf < 4; mf++)
#pragma unroll
                    for (int nf = 0; nf < 4; nf++)
                        mma8(acc[mf][nf], ah[mf], bl[nf]);
                // pass 3: lo*hi
#pragma unroll
                for (int mf = 0; mf < 4; mf++)
#pragma unroll
                    for (int nf = 0; nf < 4; nf++)
                        mma8(acc[mf][nf], al[mf], bh[nf]);
            }
        }
        if (kt + 1 < NT) {
            const int nb = ((kt + 1) & 1) * TILE_U32;
            uint4 h;
            h = hi4(pa0); *(uint4*)&Ah[nb + sr * AP + sc] = h;
            if (three) *(uint4*)&Al[nb + sr * AP + sc] = lo4(pa0, h);
            h = hi4(pa1); *(uint4*)&Ah[nb + (sr + 64) * AP + sc] = h;
            if (three) *(uint4*)&Al[nb + (sr + 64) * AP + sc] = lo4(pa1, h);
            h = hi4(pw0); *(uint4*)&Bh[nb + sr * AP + sc] = h;
            if (three) *(uint4*)&Bl[nb + sr * AP + sc] = lo4(pw0, h);
            h = hi4(pw1); *(uint4*)&Bh[nb + (sr + 64) * AP + sc] = h;
            if (three) *(uint4*)&Bl[nb + (sr + 64) * AP + sc] = lo4(pw1, h);
        }
        __syncthreads();
    }

#pragma unroll
    for (int mf = 0; mf < 4; mf++) {
#pragma unroll
        for (int nf = 0; nf < 4; nf++) {
            int m = bm * 128 + wm * 64 + mf * 16 + g;
            int n = bn * 128 + wn * 32 + nf * 8 + 2 * t;
            float2 v0 = make_float2(acc[mf][nf][0], acc[mf][nf][1]);
            float2 v1 = make_float2(acc[mf][nf][2], acc[mf][nf][3]);
            int b = m >> 12, h = n >> 6, d = n & 63;
            int s0 = m & (SEQ - 1);
            float* p = Out + (u64)((b * NUM_HEADS + h) * SEQ) * HD + d;
            *(float2*)(p + (u64)s0 * HD)       = v0;
            *(float2*)(p + (u64)(s0 + 8) * HD) = v1;
        }
    }
}

// =====================================================================
// Output-projection GEMM (single tf32), C[M,N] = A[M,K] * W[N,K]^T.
// =====================================================================
__global__ void __launch_bounds__(256, 2) gemm_out(
    const float* __restrict__ A, const float* __restrict__ W, float* __restrict__ Out)
{
    extern __shared__ u32 sh[];
    u32* Ah = sh;
    u32* Bh = Ah + 2 * TILE_U32;

    const int tid  = threadIdx.x;
    const int lane = tid & 31, wid = tid >> 5;
    const int g = lane >> 2, t = lane & 3;
    const int wm = wid >> 2, wn = wid & 3;
    const int bm = blockIdx.y, bn = blockIdx.x;

    const int sr = tid >> 2;
    const int sc = (tid & 3) << 2;

    const float* Ag = A + (u64)(bm * 128 + sr) * DMODEL + sc;
    const float* Wg = W + (u64)(bn * 128 + sr) * DMODEL + sc;

    float acc[4][4][4];
#pragma unroll
    for (int i = 0; i < 4; i++)
#pragma unroll
        for (int j = 0; j < 4; j++)
#pragma unroll
            for (int c = 0; c < 4; c++) acc[i][j][c] = 0.f;

    {
        float4 a0 = *(const float4*)(Ag);
        float4 a1 = *(const float4*)(Ag + 64 * DMODEL);
        float4 w0 = *(const float4*)(Wg);
        float4 w1 = *(const float4*)(Wg + 64 * DMODEL);
        *(uint4*)&Ah[sr * AP + sc]        = hi4(a0);
        *(uint4*)&Ah[(sr + 64) * AP + sc] = hi4(a1);
        *(uint4*)&Bh[sr * AP + sc]        = hi4(w0);
        *(uint4*)&Bh[(sr + 64) * AP + sc] = hi4(w1);
    }
    __syncthreads();

    const int NT = DMODEL / 16;
#pragma unroll 1
    for (int kt = 0; kt < NT; kt++) {
        float4 pa0, pa1, pw0, pw1;
        if (kt + 1 < NT) {
            const float* Ap = Ag + (kt + 1) * 16;
            const float* Wp = Wg + (kt + 1) * 16;
            pa0 = *(const float4*)(Ap);
            pa1 = *(const float4*)(Ap + 64 * DMODEL);
            pw0 = *(const float4*)(Wp);
            pw1 = *(const float4*)(Wp + 64 * DMODEL);
        }
        const int base = (kt & 1) * TILE_U32;
#pragma unroll
        for (int k8 = 0; k8 < 2; k8++) {
            const int co = k8 * 8 + t;
            u32 ah[4][4];
#pragma unroll
            for (int mf = 0; mf < 4; mf++) {
                int r0 = wm * 64 + mf * 16 + g;
                ah[mf][0] = Ah[base + r0 * AP + co];
                ah[mf][1] = Ah[base + (r0 + 8) * AP + co];
                ah[mf][2] = Ah[base + r0 * AP + co + 4];
                ah[mf][3] = Ah[base + (r0 + 8) * AP + co + 4];
            }
            u32 bh[4][2];
#pragma unroll
            for (int nf = 0; nf < 4; nf++) {
                int rn = wn * 32 + nf * 8 + g;
                bh[nf][0] = Bh[base + rn * AP + co];
                bh[nf][1] = Bh[base + rn * AP + co + 4];
            }
#pragma unroll
            for (int mf = 0; mf < 4; mf++)
#pragma unroll
                for (int nf = 0; nf < 4; nf++)
                    mma8(acc[mf][nf], ah[mf], bh[nf]);
        }
        if (kt + 1 < NT) {
            const int nb = ((kt + 1) & 1) * TILE_U32;
            *(uint4*)&Ah[nb + sr * AP + sc]        = hi4(pa0);
            *(uint4*)&Ah[nb + (sr + 64) * AP + sc] = hi4(pa1);
            *(uint4*)&Bh[nb + sr * AP + sc]        = hi4(pw0);
            *(uint4*)&Bh[nb + (sr + 64) * AP + sc] = hi4(pw1);
        }
        __syncthreads();
    }

#pragma unroll
    for (int mf = 0; mf < 4; mf++) {
#pragma unroll
        for (int nf = 0; nf < 4; nf++) {
            int m = bm * 128 + wm * 64 + mf * 16 + g;
            int n = bn * 128 + wn * 32 + nf * 8 + 2 * t;
            *(float2*)(Out + (u64)m * DMODEL + n) =
                make_float2(acc[mf][nf][0], acc[mf][nf][1]);
            *(float2*)(Out + (u64)(m + 8) * DMODEL + n) =
                make_float2(acc[mf][nf][2], acc[mf][nf][3]);
        }
    }
}

// =====================================================================
// Causal flash attention (exact R13 kernel — proven 1030 us).
// QK^T 3xTF32 (Q-lo in registers), softmax fp32 base-2, P·V tf32 with
// C->A frag relayout via warp shuffles. 88KB smem, 2 CTAs/SM.
// =====================================================================
#define QP 68   // pitch of Qh/Kh/Kl (4g+t bank pattern: conflict-free)
#define VP 72   // pitch of Vs (8t+8nf+g pattern: conflict-free)
#define ATSM ((128 * QP + 2 * 64 * QP + 64 * VP) * 4)   // 88064 B

__global__ void __launch_bounds__(256, 2) attn_tf32(
    const float* __restrict__ Q,
    const float* __restrict__ K,
    const float* __restrict__ V,
    float* __restrict__ O)
{
    extern __shared__ u32 sh[];
    u32* Qh = sh;                  // [128][QP]
    u32* Kh = Qh + 128 * QP;       // [64][QP]
    u32* Kl = Kh + 64 * QP;        // [64][QP]
    u32* Vs = Kl + 64 * QP;        // [64][VP]
    u32* Qltmp = Kh;               // Q-lo staging reuses K region

    const int tid  = threadIdx.x;
    const int lane = tid & 31, wid = tid >> 5;
    const int g = lane >> 2, t = lane & 3;
    const int qi = (gridDim.x - 1) - blockIdx.x;   // longest-work CTAs first
    const int bh = blockIdx.y;
    const int q0 = qi * 128;
    const int r0 = wid * 16 + g;

    const float* Qbh = Q + (u64)bh * SEQ * HD;
    const float* Kbh = K + (u64)bh * SEQ * HD;
    const float* Vbh = V + (u64)bh * SEQ * HD;

    const float QSCALE = 0.125f * 1.4426950408889634f;  // 1/sqrt(64)*log2(e)

#pragma unroll
    for (int kk = 0; kk < 8; kk++) {
        int it = tid + kk * 256;
        int r = it >> 4;
        int c4 = (it & 15) << 2;
        float4 v = *(const float4*)(Qbh + (u64)(q0 + r) * HD + c4);
        v.x *= QSCALE; v.y *= QSCALE; v.z *= QSCALE; v.w *= QSCALE;
        uint4 h = hi4(v);
        *(uint4*)&Qh[r * QP + c4] = h;
        *(uint4*)&Qltmp[r * QP + c4] = lo4(v, h);
    }
    __syncthreads();

    u32 ql[8][4];
#pragma unroll
    for (int k8 = 0; k8 < 8; k8++) {
        const int co = k8 * 8 + t;
        ql[k8][0] = Qltmp[r0 * QP + co];
        ql[k8][1] = Qltmp[(r0 + 8) * QP + co];
        ql[k8][2] = Qltmp[r0 * QP + co + 4];
        ql[k8][3] = Qltmp[(r0 + 8) * QP + co + 4];
    }
    __syncthreads();

    float of[8][4];
    float m_i[2], l_i[2];
#pragma unroll
    for (int nf = 0; nf < 8; nf++)
#pragma unroll
        for (int c = 0; c < 4; c++) of[nf][c] = 0.f;
    m_i[0] = m_i[1] = -1e30f;
    l_i[0] = l_i[1] = 0.f;

    const int NJ = 2 * qi + 2;
    for (int jt = 0; jt < NJ; jt++) {
        const int j0 = jt * 64;

#pragma unroll
        for (int kk = 0; kk < 4; kk++) {
            int it = tid + kk * 256;
            int r = it >> 4;
            int c4 = (it & 15) << 2;
            float4 kv = *(const float4*)(Kbh + (u64)(j0 + r) * HD + c4);
            uint4 h = hi4(kv);
            *(uint4*)&Kh[r * QP + c4] = h;
            *(uint4*)&Kl[r * QP + c4] = lo4(kv, h);
            float4 vv = *(const float4*)(Vbh + (u64)(j0 + r) * HD + c4);
            *(uint4*)&Vs[r * VP + c4] = hi4(vv);
        }
        __syncthreads();

        float sf[8][4];
#pragma unroll
        for (int nf = 0; nf < 8; nf++)
#pragma unroll
            for (int c = 0; c < 4; c++) sf[nf][c] = 0.f;

#pragma unroll
        for (int k8 = 0; k8 < 8; k8++) {
            const int co = k8 * 8 + t;
            u32 ah[4];
            ah[0] = Qh[r0 * QP + co];       ah[1] = Qh[(r0 + 8) * QP + co];
            ah[2] = Qh[r0 * QP + co + 4];   ah[3] = Qh[(r0 + 8) * QP + co + 4];
#pragma unroll
            for (int nf = 0; nf < 8; nf++) {
                int rn = nf * 8 + g;
                u32 bhh[2] = { Kh[rn * QP + co], Kh[rn * QP + co + 4] };
                u32 bll[2] = { Kl[rn * QP + co], Kl[rn * QP + co + 4] };
                mma8(sf[nf], ah, bhh);
                mma8(sf[nf], ah, bll);
                mma8(sf[nf], ql[k8], bhh);
            }
        }

        if (jt >= 2 * qi) {
            int rg0 = q0 + r0, rg1 = rg0 + 8;
#pragma unroll
            for (int nf = 0; nf < 8; nf++) {
                int c0 = j0 + nf * 8 + 2 * t;
                if (c0     > rg0) sf[nf][0] = -1e30f;
                if (c0 + 1 > rg0) sf[nf][1] = -1e30f;
                if (c0     > rg1) sf[nf][2] = -1e30f;
                if (c0 + 1 > rg1) sf[nf][3] = -1e30f;
            }
        }

#pragma unroll
        for (int r = 0; r < 2; r++) {
            float mx = -1e30f;
#pragma unroll
            for (int nf = 0; nf < 8; nf++)
                mx = fmaxf(mx, fmaxf(sf[nf][2 * r], sf[nf][2 * r + 1]));
            mx = fmaxf(mx, __shfl_xor_sync(0xffffffffu, mx, 1));
            mx = fmaxf(mx, __shfl_xor_sync(0xffffffffu, mx, 2));
            float mn = fmaxf(m_i[r], mx);
            float alpha = ex2f(m_i[r] - mn);
            float rs = 0.f;
#pragma unroll
            for (int nf = 0; nf < 8; nf++) {
                float p0 = ex2f(sf[nf][2 * r] - mn);
                float p1 = ex2f(sf[nf][2 * r + 1] - mn);
                sf[nf][2 * r] = p0; sf[nf][2 * r + 1] = p1;
                rs += p0 + p1;
            }
            rs += __shfl_xor_sync(0xffffffffu, rs, 1);
            rs += __shfl_xor_sync(0xffffffffu, rs, 2);
            l_i[r] = l_i[r] * alpha + rs;
            m_i[r] = mn;
#pragma unroll
            for (int nf = 0; nf < 8; nf++) {
                of[nf][2 * r]     *= alpha;
                of[nf][2 * r + 1] *= alpha;
            }
        }

        u32 pt[8][4];
#pragma unroll
        for (int nf = 0; nf < 8; nf++)
#pragma unroll
            for (int c = 0; c < 4; c++) pt[nf][c] = tf32r(sf[nf][c]);

        const int srcA = (lane & 28) | (t >> 1);

#pragma unroll
        for (int k8 = 0; k8 < 8; k8++) {
            u32 pa[4], v0, v1;
            v0 = __shfl_sync(0xffffffffu, pt[k8][0], srcA);
            v1 = __shfl_sync(0xffffffffu, pt[k8][1], srcA);
            pa[0] = (t & 1) ? v1 : v0;
            v0 = __shfl_sync(0xffffffffu, pt[k8][2], srcA);
            v1 = __shfl_sync(0xffffffffu, pt[k8][3], srcA);
            pa[1] = (t & 1) ? v1 : v0;
            v0 = __shfl_sync(0xffffffffu, pt[k8][0], srcA + 2);
            v1 = __shfl_sync(0xffffffffu, pt[k8][1], srcA + 2);
            pa[2] = (t & 1) ? v1 : v0;
            v0 = __shfl_sync(0xffffffffu, pt[k8][2], srcA + 2);
            v1 = __shfl_sync(0xffffffffu, pt[k8][3], srcA + 2);
            pa[3] = (t & 1) ? v1 : v0;
#pragma unroll
            for (int nf = 0; nf < 8; nf++) {
                u32 vb[2] = { Vs[(k8 * 8 + t) * VP + nf * 8 + g],
                              Vs[(k8 * 8 + t + 4) * VP + nf * 8 + g] };
                mma8(of[nf], pa, vb);
            }
        }
        __syncthreads();
    }

    const int b = bh >> 4, h = bh & 15;
#pragma unroll
    for (int r = 0; r < 2; r++) {
        float inv = 1.0f / l_i[r];
        int row = q0 + r0 + 8 * r;
        float* p = O + (u64)(b * SEQ + row) * DMODEL + h * HD;
#pragma unroll
        for (int nf = 0; nf < 8; nf++) {
            *(float2*)(p + nf * 8 + 2 * t) =
                make_float2(of[nf][2 * r] * inv, of[nf][2 * r + 1] * inv);
        }
    }
}

// =====================================================================
extern "C" void kernel_launch(void* const* d_in, const int* in_sizes, int n_in,
                              void* d_out, int out_size)
{
    (void)in_sizes; (void)n_in; (void)out_size;
    const float* X  = (const float*)d_in[0];
    const float* Wq = (const float*)d_in[1];
    const float* Wk = (const float*)d_in[2];
    const float* Wv = (const float*)d_in[3];
    const float* Wo = (const float*)d_in[4];
    float* out = (float*)d_out;

    float *gq, *gk, *gv, *ga;
    cudaGetSymbolAddress((void**)&gq, g_q);
    cudaGetSymbolAddress((void**)&gk, g_k);
    cudaGetSymbolAddress((void**)&gv, g_v);
    cudaGetSymbolAddress((void**)&ga, g_attn);

    cudaFuncSetAttribute(gemm_qkv, cudaFuncAttributeMaxDynamicSharedMemorySize, GSM3);
    cudaFuncSetAttribute(gemm_out, cudaFuncAttributeMaxDynamicSharedMemorySize, GSM1);
    cudaFuncSetAttribute(attn_tf32, cudaFuncAttributeMaxDynamicSharedMemorySize, ATSM);

    // 1) merged Q/K/V projections (Q,K: 3xTF32; V: single tf32)
    gemm_qkv<<<dim3(DMODEL / 128, (BATCH * SEQ) / 128, 3), 256, GSM3>>>(
        X, Wq, Wk, Wv, gq, gk, gv);

    // 2) causal flash attention -> g_attn [B,S,D]
    attn_tf32<<<dim3(SEQ / 128, BATCH * NUM_HEADS), 256, ATSM>>>(gq, gk, gv, ga);

    // 3) output projection -> d_out (single tf32)
    gemm_out<<<dim3(DMODEL / 128, (BATCH * SEQ) / 128), 256, GSM1>>>(ga, Wo, out);
}

// round 16
// speedup vs baseline: 1.5306x; 1.2555x over previous
#include <cuda_runtime.h>

typedef unsigned int u32;
typedef unsigned long long u64;

#define NUM_HEADS 16
#define BATCH     2
#define SEQ       4096
#define DMODEL    1024
#define HD        64

// ---- scratch (device globals: no allocation anywhere) ----
__device__ float g_q[BATCH * NUM_HEADS * SEQ * HD];      // [B,H,S,hd]
__device__ float g_k[BATCH * NUM_HEADS * SEQ * HD];
__device__ float g_v[BATCH * NUM_HEADS * SEQ * HD];
__device__ float g_attn[BATCH * SEQ * DMODEL];           // [B,S,D]

// ---- helpers ----
__device__ __forceinline__ u32 tf32r(float x) {
    u32 r; asm("cvt.rna.tf32.f32 %0, %1;" : "=r"(r) : "f"(x)); return r;
}
__device__ __forceinline__ float ex2f(float x) {
    float y; asm("ex2.approx.f32 %0, %1;" : "=f"(y) : "f"(x)); return y;
}
// D += A(16x8 tf32) * B(8x8 tf32), fp32 accum
__device__ __forceinline__ void mma8(float* d, const u32* a, const u32* b) {
    asm("mma.sync.aligned.m16n8k8.row.col.f32.tf32.tf32.f32 "
        "{%0,%1,%2,%3}, {%4,%5,%6,%7}, {%8,%9}, {%0,%1,%2,%3};"
        : "+f"(d[0]), "+f"(d[1]), "+f"(d[2]), "+f"(d[3])
        : "r"(a[0]), "r"(a[1]), "r"(a[2]), "r"(a[3]), "r"(b[0]), "r"(b[1]));
}
__device__ __forceinline__ uint4 hi4(const float4& v) {
    uint4 h; h.x = tf32r(v.x); h.y = tf32r(v.y); h.z = tf32r(v.z); h.w = tf32r(v.w);
    return h;
}
__device__ __forceinline__ uint4 lo4(const float4& v, const uint4& h) {
    uint4 l;
    l.x = tf32r(v.x - __uint_as_float(h.x));
    l.y = tf32r(v.y - __uint_as_float(h.y));
    l.z = tf32r(v.z - __uint_as_float(h.z));
    l.w = tf32r(v.w - __uint_as_float(h.w));
    return l;
}

// =====================================================================
// GEMM: C[M,N] = A[M,K] * W[N,K]^T, K=1024, via m16n8k8 tf32 MMA.
// R13 structure (separate launches, 128x128 tile, 2 CTAs/SM) with ONE
// change: 3xTF32 MMAs issued as 3 passes over the 16 (mf,nf) tiles ->
// accumulator dependency distance 16 instead of 1. Bit-identical math.
// =====================================================================
#define AP 20
#define TILE_U32 (128 * AP)
#define GSM1 (4 * TILE_U32 * 4)
#define GSM3 (8 * TILE_U32 * 4)

template<int QKV, int THREE>
__global__ void __launch_bounds__(256, 2) gemm_tf32(
    const float* __restrict__ A, const float* __restrict__ W, float* __restrict__ Out)
{
    extern __shared__ u32 sh[];
    u32* Ah = sh;
    u32* Bh = Ah + 2 * TILE_U32;
    u32* Al = Bh + 2 * TILE_U32;
    u32* Bl = Al + 2 * TILE_U32;

    const int tid  = threadIdx.x;
    const int lane = tid & 31, wid = tid >> 5;
    const int g = lane >> 2, t = lane & 3;
    const int wm = wid >> 2, wn = wid & 3;
    const int bm = blockIdx.y, bn = blockIdx.x;

    const int sr = tid >> 2;
    const int sc = (tid & 3) << 2;

    const float* Ag = A + (u64)(bm * 128 + sr) * DMODEL + sc;
    const float* Wg = W + (u64)(bn * 128 + sr) * DMODEL + sc;

    float acc[4][4][4];
#pragma unroll
    for (int i = 0; i < 4; i++)
#pragma unroll
        for (int j = 0; j < 4; j++)
#pragma unroll
            for (int c = 0; c < 4; c++) acc[i][j][c] = 0.f;

    {
        float4 a0 = *(const float4*)(Ag);
        float4 a1 = *(const float4*)(Ag + 64 * DMODEL);
        float4 w0 = *(const float4*)(Wg);
        float4 w1 = *(const float4*)(Wg + 64 * DMODEL);
        uint4 h;
        h = hi4(a0); *(uint4*)&Ah[sr * AP + sc] = h;
        if (THREE) *(uint4*)&Al[sr * AP + sc] = lo4(a0, h);
        h = hi4(a1); *(uint4*)&Ah[(sr + 64) * AP + sc] = h;
        if (THREE) *(uint4*)&Al[(sr + 64) * AP + sc] = lo4(a1, h);
        h = hi4(w0); *(uint4*)&Bh[sr * AP + sc] = h;
        if (THREE) *(uint4*)&Bl[sr * AP + sc] = lo4(w0, h);
        h = hi4(w1); *(uint4*)&Bh[(sr + 64) * AP + sc] = h;
        if (THREE) *(uint4*)&Bl[(sr + 64) * AP + sc] = lo4(w1, h);
    }
    __syncthreads();

    const int NT = DMODEL / 16;
#pragma unroll 1
    for (int kt = 0; kt < NT; kt++) {
        float4 pa0, pa1, pw0, pw1;
        if (kt + 1 < NT) {
            const float* Ap = Ag + (kt + 1) * 16;
            const float* Wp = Wg + (kt + 1) * 16;
            pa0 = *(const float4*)(Ap);
            pa1 = *(const float4*)(Ap + 64 * DMODEL);
            pw0 = *(const float4*)(Wp);
            pw1 = *(const float4*)(Wp + 64 * DMODEL);
        }
        const int base = (kt & 1) * TILE_U32;
#pragma unroll
        for (int k8 = 0; k8 < 2; k8++) {
            const int co = k8 * 8 + t;
            u32 ah[4][4], al[4][4];
#pragma unroll
            for (int mf = 0; mf < 4; mf++) {
                int r0 = wm * 64 + mf * 16 + g;
                ah[mf][0] = Ah[base + r0 * AP + co];
                ah[mf][1] = Ah[base + (r0 + 8) * AP + co];
                ah[mf][2] = Ah[base + r0 * AP + co + 4];
                ah[mf][3] = Ah[base + (r0 + 8) * AP + co + 4];
                if (THREE) {
                    al[mf][0] = Al[base + r0 * AP + co];
                    al[mf][1] = Al[base + (r0 + 8) * AP + co];
                    al[mf][2] = Al[base + r0 * AP + co + 4];
                    al[mf][3] = Al[base + (r0 + 8) * AP + co + 4];
                }
            }
            u32 bh[4][2], bl[4][2];
#pragma unroll
            for (int nf = 0; nf < 4; nf++) {
                int rn = wn * 32 + nf * 8 + g;
                bh[nf][0] = Bh[base + rn * AP + co];
                bh[nf][1] = Bh[base + rn * AP + co + 4];
                if (THREE) {
                    bl[nf][0] = Bl[base + rn * AP + co];
                    bl[nf][1] = Bl[base + rn * AP + co + 4];
                }
            }
            // pass 1: hi*hi  (accumulator reuse distance = 16)
#pragma unroll
            for (int mf = 0; mf < 4; mf++)
#pragma unroll
                for (int nf = 0; nf < 4; nf++)
                    mma8(acc[mf][nf], ah[mf], bh[nf]);
            if (THREE) {
                // pass 2: hi*lo
#pragma unroll
                for (int mf = 0; mf < 4; mf++)
#pragma unroll
                    for (int nf = 0; nf < 4; nf++)
                        mma8(acc[mf][nf], ah[mf], bl[nf]);
                // pass 3: lo*hi
#pragma unroll
                for (int mf = 0; mf < 4; mf++)
#pragma unroll
                    for (int nf = 0; nf < 4; nf++)
                        mma8(acc[mf][nf], al[mf], bh[nf]);
            }
        }
        if (kt + 1 < NT) {
            const int nb = ((kt + 1) & 1) * TILE_U32;
            uint4 h;
            h = hi4(pa0); *(uint4*)&Ah[nb + sr * AP + sc] = h;
            if (THREE) *(uint4*)&Al[nb + sr * AP + sc] = lo4(pa0, h);
            h = hi4(pa1); *(uint4*)&Ah[nb + (sr + 64) * AP + sc] = h;
            if (THREE) *(uint4*)&Al[nb + (sr + 64) * AP + sc] = lo4(pa1, h);
            h = hi4(pw0); *(uint4*)&Bh[nb + sr * AP + sc] = h;
            if (THREE) *(uint4*)&Bl[nb + sr * AP + sc] = lo4(pw0, h);
            h = hi4(pw1); *(uint4*)&Bh[nb + (sr + 64) * AP + sc] = h;
            if (THREE) *(uint4*)&Bl[nb + (sr + 64) * AP + sc] = lo4(pw1, h);
        }
        __syncthreads();
    }

#pragma unroll
    for (int mf = 0; mf < 4; mf++) {
#pragma unroll
        for (int nf = 0; nf < 4; nf++) {
            int m = bm * 128 + wm * 64 + mf * 16 + g;
            int n = bn * 128 + wn * 32 + nf * 8 + 2 * t;
            float2 v0 = make_float2(acc[mf][nf][0], acc[mf][nf][1]);
            float2 v1 = make_float2(acc[mf][nf][2], acc[mf][nf][3]);
            if (QKV) {
                int b = m >> 12, h = n >> 6, d = n & 63;
                int s0 = m & (SEQ - 1);
                float* p = Out + (u64)((b * NUM_HEADS + h) * SEQ) * HD + d;
                *(float2*)(p + (u64)s0 * HD)       = v0;
                *(float2*)(p + (u64)(s0 + 8) * HD) = v1;
            } else {
                *(float2*)(Out + (u64)m * DMODEL + n)       = v0;
                *(float2*)(Out + (u64)(m + 8) * DMODEL + n) = v1;
            }
        }
    }
}

// =====================================================================
// Causal flash attention (exact R13 kernel — proven 1030 us).
// QK^T 3xTF32 (Q-lo in registers), softmax fp32 base-2, P·V tf32 with
// C->A frag relayout via warp shuffles. 88KB smem, 2 CTAs/SM.
// =====================================================================
#define QP 68   // pitch of Qh/Kh/Kl (4g+t bank pattern: conflict-free)
#define VP 72   // pitch of Vs (8t+8nf+g pattern: conflict-free)
#define ATSM ((128 * QP + 2 * 64 * QP + 64 * VP) * 4)   // 88064 B

__global__ void __launch_bounds__(256, 2) attn_tf32(
    const float* __restrict__ Q,
    const float* __restrict__ K,
    const float* __restrict__ V,
    float* __restrict__ O)
{
    extern __shared__ u32 sh[];
    u32* Qh = sh;                  // [128][QP]
    u32* Kh = Qh + 128 * QP;       // [64][QP]
    u32* Kl = Kh + 64 * QP;        // [64][QP]
    u32* Vs = Kl + 64 * QP;        // [64][VP]
    u32* Qltmp = Kh;               // Q-lo staging reuses K region

    const int tid  = threadIdx.x;
    const int lane = tid & 31, wid = tid >> 5;
    const int g = lane >> 2, t = lane & 3;
    const int qi = (gridDim.x - 1) - blockIdx.x;   // longest-work CTAs first
    const int bh = blockIdx.y;
    const int q0 = qi * 128;
    const int r0 = wid * 16 + g;

    const float* Qbh = Q + (u64)bh * SEQ * HD;
    const float* Kbh = K + (u64)bh * SEQ * HD;
    const float* Vbh = V + (u64)bh * SEQ * HD;

    const float QSCALE = 0.125f * 1.4426950408889634f;  // 1/sqrt(64)*log2(e)

#pragma unroll
    for (int kk = 0; kk < 8; kk++) {
        int it = tid + kk * 256;
        int r = it >> 4;
        int c4 = (it & 15) << 2;
        float4 v = *(const float4*)(Qbh + (u64)(q0 + r) * HD + c4);
        v.x *= QSCALE; v.y *= QSCALE; v.z *= QSCALE; v.w *= QSCALE;
        uint4 h = hi4(v);
        *(uint4*)&Qh[r * QP + c4] = h;
        *(uint4*)&Qltmp[r * QP + c4] = lo4(v, h);
    }
    __syncthreads();

    u32 ql[8][4];
#pragma unroll
    for (int k8 = 0; k8 < 8; k8++) {
        const int co = k8 * 8 + t;
        ql[k8][0] = Qltmp[r0 * QP + co];
        ql[k8][1] = Qltmp[(r0 + 8) * QP + co];
        ql[k8][2] = Qltmp[r0 * QP + co + 4];
        ql[k8][3] = Qltmp[(r0 + 8) * QP + co + 4];
    }
    __syncthreads();

    float of[8][4];
    float m_i[2], l_i[2];
#pragma unroll
    for (int nf = 0; nf < 8; nf++)
#pragma unroll
        for (int c = 0; c < 4; c++) of[nf][c] = 0.f;
    m_i[0] = m_i[1] = -1e30f;
    l_i[0] = l_i[1] = 0.f;

    const int NJ = 2 * qi + 2;
    for (int jt = 0; jt < NJ; jt++) {
        const int j0 = jt * 64;

#pragma unroll
        for (int kk = 0; kk < 4; kk++) {
            int it = tid + kk * 256;
            int r = it >> 4;
            int c4 = (it & 15) << 2;
            float4 kv = *(const float4*)(Kbh + (u64)(j0 + r) * HD + c4);
            uint4 h = hi4(kv);
            *(uint4*)&Kh[r * QP + c4] = h;
            *(uint4*)&Kl[r * QP + c4] = lo4(kv, h);
            float4 vv = *(const float4*)(Vbh + (u64)(j0 + r) * HD + c4);
            *(uint4*)&Vs[r * VP + c4] = hi4(vv);
        }
        __syncthreads();

        float sf[8][4];
#pragma unroll
        for (int nf = 0; nf < 8; nf++)
#pragma unroll
            for (int c = 0; c < 4; c++) sf[nf][c] = 0.f;

#pragma unroll
        for (int k8 = 0; k8 < 8; k8++) {
            const int co = k8 * 8 + t;
            u32 ah[4];
            ah[0] = Qh[r0 * QP + co];       ah[1] = Qh[(r0 + 8) * QP + co];
            ah[2] = Qh[r0 * QP + co + 4];   ah[3] = Qh[(r0 + 8) * QP + co + 4];
#pragma unroll
            for (int nf = 0; nf < 8; nf++) {
                int rn = nf * 8 + g;
                u32 bhh[2] = { Kh[rn * QP + co], Kh[rn * QP + co + 4] };
                u32 bll[2] = { Kl[rn * QP + co], Kl[rn * QP + co + 4] };
                mma8(sf[nf], ah, bhh);
                mma8(sf[nf], ah, bll);
                mma8(sf[nf], ql[k8], bhh);
            }
        }

        if (jt >= 2 * qi) {
            int rg0 = q0 + r0, rg1 = rg0 + 8;
#pragma unroll
            for (int nf = 0; nf < 8; nf++) {
                int c0 = j0 + nf * 8 + 2 * t;
                if (c0     > rg0) sf[nf][0] = -1e30f;
                if (c0 + 1 > rg0) sf[nf][1] = -1e30f;
                if (c0     > rg1) sf[nf][2] = -1e30f;
                if (c0 + 1 > rg1) sf[nf][3] = -1e30f;
            }
        }

#pragma unroll
        for (int r = 0; r < 2; r++) {
            float mx = -1e30f;
#pragma unroll
            for (int nf = 0; nf < 8; nf++)
                mx = fmaxf(mx, fmaxf(sf[nf][2 * r], sf[nf][2 * r + 1]));
            mx = fmaxf(mx, __shfl_xor_sync(0xffffffffu, mx, 1));
            mx = fmaxf(mx, __shfl_xor_sync(0xffffffffu, mx, 2));
            float mn = fmaxf(m_i[r], mx);
            float alpha = ex2f(m_i[r] - mn);
            float rs = 0.f;
#pragma unroll
            for (int nf = 0; nf < 8; nf++) {
                float p0 = ex2f(sf[nf][2 * r] - mn);
                float p1 = ex2f(sf[nf][2 * r + 1] - mn);
                sf[nf][2 * r] = p0; sf[nf][2 * r + 1] = p1;
                rs += p0 + p1;
            }
            rs += __shfl_xor_sync(0xffffffffu, rs, 1);
            rs += __shfl_xor_sync(0xffffffffu, rs, 2);
            l_i[r] = l_i[r] * alpha + rs;
            m_i[r] = mn;
#pragma unroll
            for (int nf = 0; nf < 8; nf++) {
                of[nf][2 * r]     *= alpha;
                of[nf][2 * r + 1] *= alpha;
            }
        }

        u32 pt[8][4];
#pragma unroll
        for (int nf = 0; nf < 8; nf++)
#pragma unroll
            for (int c = 0; c < 4; c++) pt[nf][c] = tf32r(sf[nf][c]);

        const int srcA = (lane & 28) | (t >> 1);

#pragma unroll
        for (int k8 = 0; k8 < 8; k8++) {
            u32 pa[4], v0, v1;
            v0 = __shfl_sync(0xffffffffu, pt[k8][0], srcA);
            v1 = __shfl_sync(0xffffffffu, pt[k8][1], srcA);
            pa[0] = (t & 1) ? v1 : v0;
            v0 = __shfl_sync(0xffffffffu, pt[k8][2], srcA);
            v1 = __shfl_sync(0xffffffffu, pt[k8][3], srcA);
            pa[1] = (t & 1) ? v1 : v0;
            v0 = __shfl_sync(0xffffffffu, pt[k8][0], srcA + 2);
            v1 = __shfl_sync(0xffffffffu, pt[k8][1], srcA + 2);
            pa[2] = (t & 1) ? v1 : v0;
            v0 = __shfl_sync(0xffffffffu, pt[k8][2], srcA + 2);
            v1 = __shfl_sync(0xffffffffu, pt[k8][3], srcA + 2);
            pa[3] = (t & 1) ? v1 : v0;
#pragma unroll
            for (int nf = 0; nf < 8; nf++) {
                u32 vb[2] = { Vs[(k8 * 8 + t) * VP + nf * 8 + g],
                              Vs[(k8 * 8 + t + 4) * VP + nf * 8 + g] };
                mma8(of[nf], pa, vb);
            }
        }
        __syncthreads();
    }

    const int b = bh >> 4, h = bh & 15;
#pragma unroll
    for (int r = 0; r < 2; r++) {
        float inv = 1.0f / l_i[r];
        int row = q0 + r0 + 8 * r;
        float* p = O + (u64)(b * SEQ + row) * DMODEL + h * HD;
#pragma unroll
        for (int nf = 0; nf < 8; nf++) {
            *(float2*)(p + nf * 8 + 2 * t) =
                make_float2(of[nf][2 * r] * inv, of[nf][2 * r + 1] * inv);
        }
    }
}

// =====================================================================
extern "C" void kernel_launch(void* const* d_in, const int* in_sizes, int n_in,
                              void* d_out, int out_size)
{
    (void)in_sizes; (void)n_in; (void)out_size;
    const float* X  = (const float*)d_in[0];
    const float* Wq = (const float*)d_in[1];
    const float* Wk = (const float*)d_in[2];
    const float* Wv = (const float*)d_in[3];
    const float* Wo = (const float*)d_in[4];
    float* out = (float*)d_out;

    float *gq, *gk, *gv, *ga;
    cudaGetSymbolAddress((void**)&gq, g_q);
    cudaGetSymbolAddress((void**)&gk, g_k);
    cudaGetSymbolAddress((void**)&gv, g_v);
    cudaGetSymbolAddress((void**)&ga, g_attn);

    cudaFuncSetAttribute(gemm_tf32<1,1>, cudaFuncAttributeMaxDynamicSharedMemorySize, GSM3);
    cudaFuncSetAttribute(gemm_tf32<1,0>, cudaFuncAttributeMaxDynamicSharedMemorySize, GSM1);
    cudaFuncSetAttribute(gemm_tf32<0,0>, cudaFuncAttributeMaxDynamicSharedMemorySize, GSM1);
    cudaFuncSetAttribute(attn_tf32,      cudaFuncAttributeMaxDynamicSharedMemorySize, ATSM);

    dim3 ggrid(DMODEL / 128, (BATCH * SEQ) / 128);   // (8, 64)

    // 1) projections: Q,K in 3xTF32 (score path), V single tf32 — SEPARATE
    //    launches (R15 showed merging thrashes L2)
    gemm_tf32<1,1><<<ggrid, 256, GSM3>>>(X, Wq, gq);
    gemm_tf32<1,1><<<ggrid, 256, GSM3>>>(X, Wk, gk);
    gemm_tf32<1,0><<<ggrid, 256, GSM1>>>(X, Wv, gv);

    // 2) causal flash attention -> g_attn [B,S,D]
    attn_tf32<<<dim3(SEQ / 128, BATCH * NUM_HEADS), 256, ATSM>>>(gq, gk, gv, ga);

    // 3) output projection -> d_out (single tf32)
    gemm_tf32<0,0><<<ggrid, 256, GSM1>>>(ga, Wo, out);
}